// round 1
// baseline (speedup 1.0000x reference)
#include <cuda_runtime.h>

#define EMB 1024
#define NCOL 2048          // width*modes*2
#define B_BATCH 64
#define L_FFT 8192
#define T_OUT 8190
#define NJ 128

// ---- device scratch (no allocations allowed) ----
__device__ float g_part[8 * B_BATCH * NCOL];     // split-K partials, 4MB
__device__ float g_h[B_BATCH * NCOL];            // decode_head output
__device__ float g_uv[B_BATCH * NJ * 32];        // per-batch [j][16 U | 16 V]
__device__ float g_basis[L_FFT * 32];            // per-t [16 cos | 16 sin]

// K1: token @ w_dec, split into 8 K-chunks, deterministic partials (no atomics)
__global__ void k1_gemm(const float* __restrict__ token, const float* __restrict__ wdec) {
    int c  = blockIdx.x * 256 + threadIdx.x;   // column 0..2047 (gridDim.x = 8)
    int b0 = blockIdx.y * 8;                   // batch group (8 groups)
    int e0 = blockIdx.z * 128;                 // K chunk (8 chunks)
    __shared__ float ts[8][128];
    for (int i = threadIdx.x; i < 1024; i += 256)
        ts[i >> 7][i & 127] = token[(b0 + (i >> 7)) * EMB + e0 + (i & 127)];
    __syncthreads();
    float acc[8] = {0,0,0,0,0,0,0,0};
#pragma unroll 4
    for (int e = 0; e < 128; e++) {
        float wv = wdec[(size_t)(e0 + e) * NCOL + c];
#pragma unroll
        for (int bi = 0; bi < 8; bi++) acc[bi] = fmaf(ts[bi][e], wv, acc[bi]);
    }
#pragma unroll
    for (int bi = 0; bi < 8; bi++)
        g_part[((size_t)blockIdx.z * B_BATCH + b0 + bi) * NCOL + c] = acc[bi];
}

// K1b: reduce split-K partials + bias -> h
__global__ void k1b_reduce(const float* __restrict__ bdec) {
    int i = blockIdx.x * 256 + threadIdx.x;    // 131072 elements
    float s = bdec[i & (NCOL - 1)];
#pragma unroll
    for (int ks = 0; ks < 8; ks++) s += g_part[ks * (B_BATCH * NCOL) + i];
    g_h[i] = s;
}

// K2: U[b,j,k] = sc_k * sum_w w1[w,j]*h[b,w*32+2k] ; V = -sc_k * (imag part)
__global__ void k2_uv(const float* __restrict__ w1) {
    int b = blockIdx.x;
    __shared__ float hs[NCOL];
    __shared__ float w1s[64 * NJ];
    for (int i = threadIdx.x; i < NCOL; i += 512) hs[i] = g_h[b * NCOL + i];
    for (int i = threadIdx.x; i < 64 * NJ; i += 512) w1s[i] = w1[i];
    __syncthreads();
    int j  = threadIdx.x & 127;
    int kb = (threadIdx.x >> 7) * 4;           // 0,4,8,12
    float ua[4] = {0,0,0,0}, va[4] = {0,0,0,0};
#pragma unroll 4
    for (int w = 0; w < 64; w++) {
        float wv = w1s[w * NJ + j];
#pragma unroll
        for (int kk = 0; kk < 4; kk++) {
            ua[kk] = fmaf(wv, hs[w * 32 + (kb + kk) * 2],     ua[kk]);
            va[kk] = fmaf(wv, hs[w * 32 + (kb + kk) * 2 + 1], va[kk]);
        }
    }
    const float inv = 1.0f / (float)L_FFT;
#pragma unroll
    for (int kk = 0; kk < 4; kk++) {
        int k = kb + kk;
        float sc = (k == 0) ? inv : 2.0f * inv;
        g_uv[((size_t)b * NJ + j) * 32 + k]      =  sc * ua[kk];
        g_uv[((size_t)b * NJ + j) * 32 + 16 + k] = -sc * va[kk];
    }
}

// K3: basis[t][k] = cos(2*pi*k*t/L), basis[t][16+k] = sin(...)
__global__ void k3_basis() {
    int idx = blockIdx.x * 256 + threadIdx.x;  // t*16 + k, 131072 total
    int t = idx >> 4, k = idx & 15;
    int m = (k * t) & (L_FFT - 1);
    float ang = (float)m * 7.6699039394282067e-4f;   // 2*pi/8192
    float s, c;
    sincosf(ang, &s, &c);
    g_basis[t * 32 + k] = c;
    g_basis[t * 32 + 16 + k] = s;
}

// K4: main loop. Warp-per-t; lane holds 4 j-rows of U/V in registers.
__global__ void __launch_bounds__(256) k4_main(
    const float* __restrict__ b1, const float* __restrict__ w2,
    const float* __restrict__ b2p, float* __restrict__ out) {
    int b    = blockIdx.y;
    int warp = threadIdx.x >> 5;
    int lane = threadIdx.x & 31;
    int t0   = blockIdx.x * 256 + warp * 32;

    float u[4][16], v[4][16], b1v[4], w2v[4];
#pragma unroll
    for (int jj = 0; jj < 4; jj++) {
        int j = lane * 4 + jj;
        const float4* p = (const float4*)(g_uv + ((size_t)b * NJ + j) * 32);
#pragma unroll
        for (int q = 0; q < 4; q++) {
            float4 a = p[q];
            u[jj][q*4+0]=a.x; u[jj][q*4+1]=a.y; u[jj][q*4+2]=a.z; u[jj][q*4+3]=a.w;
        }
#pragma unroll
        for (int q = 0; q < 4; q++) {
            float4 a = p[4+q];
            v[jj][q*4+0]=a.x; v[jj][q*4+1]=a.y; v[jj][q*4+2]=a.z; v[jj][q*4+3]=a.w;
        }
        b1v[jj] = b1[j];
        w2v[jj] = w2[j];
    }
    float b2v = b2p[0];

#pragma unroll 1
    for (int i = 0; i < 32; i++) {
        int t = t0 + i;
        if (t >= T_OUT) break;
        const float4* bp = (const float4*)(g_basis + (size_t)t * 32);
        float cb[16], sb[16];
#pragma unroll
        for (int q = 0; q < 4; q++) {
            float4 a = bp[q];
            cb[q*4+0]=a.x; cb[q*4+1]=a.y; cb[q*4+2]=a.z; cb[q*4+3]=a.w;
        }
#pragma unroll
        for (int q = 0; q < 4; q++) {
            float4 a = bp[4+q];
            sb[q*4+0]=a.x; sb[q*4+1]=a.y; sb[q*4+2]=a.z; sb[q*4+3]=a.w;
        }
        float acc = 0.0f;
#pragma unroll
        for (int jj = 0; jj < 4; jj++) {
            float p = b1v[jj];
#pragma unroll
            for (int k = 0; k < 16; k++) {
                p = fmaf(u[jj][k], cb[k], p);
                p = fmaf(v[jj][k], sb[k], p);
            }
            float g = 0.5f * p * (1.0f + erff(p * 0.70710678118654752f));
            acc = fmaf(g, w2v[jj], acc);
        }
#pragma unroll
        for (int off = 16; off; off >>= 1)
            acc += __shfl_xor_sync(0xffffffffu, acc, off);
        if (lane == 0) out[(size_t)b * T_OUT + t] = acc + b2v;
    }
}

extern "C" void kernel_launch(void* const* d_in, const int* in_sizes, int n_in,
                              void* d_out, int out_size) {
    const float* token = (const float*)d_in[0];
    // d_in[1] = x_len (int scalar, fixed 8192 by problem setup)
    const float* wdec  = (const float*)d_in[2];
    const float* bdec  = (const float*)d_in[3];
    const float* w1    = (const float*)d_in[4];
    const float* b1    = (const float*)d_in[5];
    const float* w2    = (const float*)d_in[6];
    const float* b2    = (const float*)d_in[7];
    float* out = (float*)d_out;

    k3_basis<<<512, 256>>>();
    k1_gemm<<<dim3(8, 8, 8), 256>>>(token, wdec);
    k1b_reduce<<<512, 256>>>(bdec);
    k2_uv<<<64, 512>>>(w1);
    k4_main<<<dim3(32, 64), 256>>>(b1, w2, b2, out);
}

// round 3
// speedup vs baseline: 1.7620x; 1.7620x over previous
#include <cuda_runtime.h>

#define EMB 1024
#define NCOL 2048          // width*modes*2
#define B_BATCH 64
#define L_FFT 8192
#define T_OUT 8190
#define NJ 128

// ---- device scratch (no allocations allowed) ----
__device__ float  g_part[8 * B_BATCH * NCOL];    // split-K partials
__device__ float  g_h[B_BATCH * NCOL];           // decode_head output
__device__ float2 g_uv[B_BATCH * NJ * 16];       // per (b,j,k): (U, V) scaled
__device__ float2 g_basis[L_FFT * 16];           // per (t,k): (cos, sin)

// ---- packed f32x2 helpers (sm_103a FFMA2 via PTX) ----
__device__ __forceinline__ unsigned long long pk2(float lo, float hi) {
    unsigned long long r;
    asm("mov.b64 %0,{%1,%2};" : "=l"(r) : "f"(lo), "f"(hi));
    return r;
}
__device__ __forceinline__ void upk2(unsigned long long v, float& lo, float& hi) {
    asm("mov.b64 {%0,%1},%2;" : "=f"(lo), "=f"(hi) : "l"(v));
}
__device__ __forceinline__ void ffma2(unsigned long long& d,
                                      unsigned long long a, unsigned long long b) {
    asm("fma.rn.f32x2 %0,%1,%2,%0;" : "+l"(d) : "l"(a), "l"(b));
}

// K1: token @ w_dec, split into 8 K-chunks, deterministic partials (no atomics)
__global__ void k1_gemm(const float* __restrict__ token, const float* __restrict__ wdec) {
    int c  = blockIdx.x * 256 + threadIdx.x;   // column 0..2047 (gridDim.x = 8)
    int b0 = blockIdx.y * 8;                   // batch group (8 groups)
    int e0 = blockIdx.z * 128;                 // K chunk (8 chunks)
    __shared__ float ts[8][128];
    for (int i = threadIdx.x; i < 1024; i += 256)
        ts[i >> 7][i & 127] = token[(b0 + (i >> 7)) * EMB + e0 + (i & 127)];
    __syncthreads();
    float acc[8] = {0,0,0,0,0,0,0,0};
#pragma unroll 4
    for (int e = 0; e < 128; e++) {
        float wv = wdec[(size_t)(e0 + e) * NCOL + c];
#pragma unroll
        for (int bi = 0; bi < 8; bi++) acc[bi] = fmaf(ts[bi][e], wv, acc[bi]);
    }
#pragma unroll
    for (int bi = 0; bi < 8; bi++)
        g_part[((size_t)blockIdx.z * B_BATCH + b0 + bi) * NCOL + c] = acc[bi];
}

// K1b: reduce split-K partials + bias -> h (grid-stride, robust)
__global__ void k1b_reduce(const float* __restrict__ bdec) {
    for (int i = blockIdx.x * blockDim.x + threadIdx.x;
         i < B_BATCH * NCOL; i += gridDim.x * blockDim.x) {
        float s = bdec[i & (NCOL - 1)];
#pragma unroll
        for (int ks = 0; ks < 8; ks++) s += g_part[ks * (B_BATCH * NCOL) + i];
        g_h[i] = s;
    }
}

// K2: U[b,j,k] = sc_k * sum_w w1[w,j]*h[b,w,2k] ; V = -sc_k * sum_w w1[w,j]*h[b,w,2k+1]
// grid (64 batches, 2 k-halves), 256 threads
__global__ void k2_uv(const float* __restrict__ w1) {
    int b = blockIdx.x;
    __shared__ float hs[NCOL];
    __shared__ float w1s[64 * NJ];
    for (int i = threadIdx.x; i < NCOL; i += 256) hs[i] = g_h[b * NCOL + i];
    for (int i = threadIdx.x; i < 64 * NJ; i += 256) w1s[i] = w1[i];
    __syncthreads();
    int j  = threadIdx.x & 127;
    int kb = ((threadIdx.x >> 7) + 2 * blockIdx.y) * 4;   // 0..12
    float ua[4] = {0,0,0,0}, va[4] = {0,0,0,0};
#pragma unroll 4
    for (int w = 0; w < 64; w++) {
        float wv = w1s[w * NJ + j];
#pragma unroll
        for (int kk = 0; kk < 4; kk++) {
            ua[kk] = fmaf(wv, hs[w * 32 + (kb + kk) * 2],     ua[kk]);
            va[kk] = fmaf(wv, hs[w * 32 + (kb + kk) * 2 + 1], va[kk]);
        }
    }
    const float inv = 1.0f / (float)L_FFT;
#pragma unroll
    for (int kk = 0; kk < 4; kk++) {
        int k = kb + kk;
        float sc = (k == 0) ? inv : 2.0f * inv;
        g_uv[((size_t)b * NJ + j) * 16 + k] = make_float2(sc * ua[kk], -sc * va[kk]);
    }
}

// K3: basis[t][k] = (cos(2*pi*k*t/L), sin(2*pi*k*t/L))
__global__ void k3_basis() {
    int idx = blockIdx.x * 256 + threadIdx.x;  // t*16 + k, 131072 total
    int t = idx >> 4, k = idx & 15;
    int m = (k * t) & (L_FFT - 1);
    float ang = (float)m * 7.6699039394282067e-4f;   // 2*pi/8192
    float s, c;
    sincosf(ang, &s, &c);
    g_basis[(size_t)t * 16 + k] = make_float2(c, s);
}

// K4: thread-per-t. UV rows broadcast from smem; packed f32x2 FMAs; no shuffles.
__global__ void __launch_bounds__(256) k4_main(
    const float* __restrict__ b1, const float* __restrict__ w2,
    const float* __restrict__ b2p, float* __restrict__ out) {
    __shared__ unsigned long long s_uv[NJ * 16];   // 16KB: (U,V) packed per (j,k)
    __shared__ float2 s_bw[NJ];                    // (b1[j], w2[j])
    int b = blockIdx.y;
    const unsigned long long* guv =
        (const unsigned long long*)(g_uv + (size_t)b * NJ * 16);
    for (int i = threadIdx.x; i < NJ * 16; i += 256) s_uv[i] = guv[i];
    if (threadIdx.x < NJ)
        s_bw[threadIdx.x] = make_float2(b1[threadIdx.x], w2[threadIdx.x]);
    __syncthreads();

    int t = blockIdx.x * 256 + threadIdx.x;
    if (t >= T_OUT) return;

    // per-thread basis: 16 packed (cos,sin) pairs = 128B, 8x LDG.128
    unsigned long long bas[16];
    const ulonglong2* gb = (const ulonglong2*)(g_basis + (size_t)t * 16);
#pragma unroll
    for (int q = 0; q < 8; q++) {
        ulonglong2 v = gb[q];
        bas[2 * q] = v.x; bas[2 * q + 1] = v.y;
    }

    float acc = b2p[0];
#pragma unroll 2
    for (int j = 0; j < NJ; j++) {
        const ulonglong2* up = (const ulonglong2*)(s_uv + j * 16);
        float2 bw = s_bw[j];
        // 4 independent packed accumulator chains (lo accumulates U*cos, hi V*sin)
        unsigned long long a0 = pk2(bw.x, 0.0f), a1 = 0ull, a2 = 0ull, a3 = 0ull;
#pragma unroll
        for (int q = 0; q < 4; q++) {
            ulonglong2 x = up[2 * q];       // k = 4q, 4q+1
            ulonglong2 y = up[2 * q + 1];   // k = 4q+2, 4q+3
            ffma2(a0, x.x, bas[4 * q + 0]);
            ffma2(a1, x.y, bas[4 * q + 1]);
            ffma2(a2, y.x, bas[4 * q + 2]);
            ffma2(a3, y.y, bas[4 * q + 3]);
        }
        float l0, h0, l1, h1, l2, h2, l3, h3;
        upk2(a0, l0, h0); upk2(a1, l1, h1);
        upk2(a2, l2, h2); upk2(a3, l3, h3);
        float p = ((l0 + h0) + (l1 + h1)) + ((l2 + h2) + (l3 + h3));
        float g = 0.5f * p * (1.0f + erff(p * 0.70710678118654752f));
        acc = fmaf(g, bw.y, acc);
    }
    out[(size_t)b * T_OUT + t] = acc;
}

extern "C" void kernel_launch(void* const* d_in, const int* in_sizes, int n_in,
                              void* d_out, int out_size) {
    const float* token = (const float*)d_in[0];
    // d_in[1] = x_len (int scalar, fixed 8192 by problem setup)
    const float* wdec  = (const float*)d_in[2];
    const float* bdec  = (const float*)d_in[3];
    const float* w1    = (const float*)d_in[4];
    const float* b1    = (const float*)d_in[5];
    const float* w2    = (const float*)d_in[6];
    const float* b2    = (const float*)d_in[7];
    float* out = (float*)d_out;

    k3_basis<<<512, 256>>>();
    k1_gemm<<<dim3(8, 8, 8), 256>>>(token, wdec);
    k1b_reduce<<<512, 256>>>(bdec);
    k2_uv<<<dim3(64, 2), 256>>>(w1);
    k4_main<<<dim3(32, 64), 256>>>(b1, w2, b2, out);
}